// round 12
// baseline (speedup 1.0000x reference)
#include <cuda_runtime.h>
#include <cuda_bf16.h>
#include <math.h>
#include <stdint.h>

// Problem constants
#define NN 4096
#define DD 1024
#define HH 2048

typedef __nv_bfloat16 bf16;

// ---------------- scratch (device globals; no allocations allowed) ----------
__device__ float g_invden[DD / 2];
__device__ float g_colsum[DD];
__device__ float g_scoresA[(size_t)NN * NN];           // 64 MB
__device__ float g_scoresB[(size_t)NN * NN];           // 64 MB

__device__ bf16 g_Xhi[(size_t)NN * DD],     g_Xlo[(size_t)NN * DD];
__device__ bf16 g_loohi[(size_t)NN * DD],   g_loolo[(size_t)NN * DD];
__device__ bf16 g_WvThi[(size_t)DD * DD],   g_WvTlo[(size_t)DD * DD];
__device__ bf16 g_W1Thi[(size_t)HH * 2*DD], g_W1Tlo[(size_t)HH * 2*DD];
__device__ bf16 g_hidhi[(size_t)NN * HH],   g_hidlo[(size_t)NN * HH];
__device__ bf16 g_W2Thi[(size_t)NN * HH],   g_W2Tlo[(size_t)NN * HH];
__device__ bf16 g_atthi[(size_t)NN * NN],   g_attlo[(size_t)NN * NN];
__device__ bf16 g_VThi[(size_t)DD * NN],    g_VTlo[(size_t)DD * NN];

// ---------------- helpers -----------------------------------------------------
__device__ __forceinline__ uint32_t smem_u32(const void* p) {
    uint32_t a;
    asm("{ .reg .u64 t; cvta.to.shared.u64 t, %1; cvt.u32.u64 %0, t; }" : "=r"(a) : "l"(p));
    return a;
}
__device__ __forceinline__ void cp_async16(uint32_t saddr, const void* gaddr) {
    asm volatile("cp.async.cg.shared.global [%0], [%1], 16;" :: "r"(saddr), "l"(gaddr));
}
__device__ __forceinline__ void cp_commit() {
    asm volatile("cp.async.commit_group;");
}
template<int N>
__device__ __forceinline__ void cp_wait() {
    asm volatile("cp.async.wait_group %0;" :: "n"(N));
}
__device__ __forceinline__ void ldsm_x4(uint32_t addr, uint32_t& r0, uint32_t& r1,
                                        uint32_t& r2, uint32_t& r3) {
    asm volatile("ldmatrix.sync.aligned.m8n8.x4.shared.b16 {%0,%1,%2,%3}, [%4];"
                 : "=r"(r0), "=r"(r1), "=r"(r2), "=r"(r3) : "r"(addr));
}
__device__ __forceinline__ void mma_bf16(float* c, const uint32_t* a, const uint32_t* b) {
    asm volatile(
        "mma.sync.aligned.m16n8k16.row.col.f32.bf16.bf16.f32 "
        "{%0,%1,%2,%3}, {%4,%5,%6,%7}, {%8,%9}, {%0,%1,%2,%3};"
        : "+f"(c[0]), "+f"(c[1]), "+f"(c[2]), "+f"(c[3])
        : "r"(a[0]), "r"(a[1]), "r"(a[2]), "r"(a[3]), "r"(b[0]), "r"(b[1]));
}

// ---------------- unified GEMM job description --------------------------------
struct GP {
    const bf16 *Ahi, *Alo, *A2hi, *A2lo;   // A row-major [M][ldA]; A2 for k>=K1
    const bf16 *Bhi, *Blo;                 // B' row-major [N][ldB]
    const float* bias;
    float* Cf;
    bf16 *Chi, *Clo;
    int gx;                                // tiles along N
    int ldA1, ldA2, ldB, ldC;
    int Kloop, K1;
    int biasmode;                          // 0 none, 1 per-col, 2 per-row
    int relu, split;
};

#define BM 128
#define BN 128
#define BK 32
#define TILE (BM * 64)               // 8192 B
#define T_AHI 0
#define T_ALO TILE
#define T_BHI (2 * TILE)
#define T_BLO (3 * TILE)
#define STAGE_BYTES (4 * TILE)       // 32768 B
#define STAGES 3
#define GSMEM (STAGES * STAGE_BYTES) // 98304 B

__device__ __forceinline__ uint32_t swz(int r, int q) {
    return (uint32_t)(r * 64 + ((q ^ ((r >> 1) & 3)) << 4));
}

__device__ __forceinline__ void load_chunk(uint32_t sstage, const GP* __restrict__ p,
                                           int kt, int cy, int cx, int tid) {
    const bf16 *Ah, *Al;
    int ka, sA;
    if (kt < p->K1) { Ah = p->Ahi;  Al = p->Alo;  ka = kt;         sA = p->ldA1; }
    else            { Ah = p->A2hi; Al = p->A2lo; ka = kt - p->K1; sA = p->ldA2; }
    const bf16* Bh = p->Bhi;
    const bf16* Bl = p->Blo;
    const int sB = p->ldB;
    #pragma unroll
    for (int i = 0; i < 2; i++) {
        int u = tid + i * 256;       // 0..511
        int r = u >> 2, q = u & 3;
        uint32_t so = swz(r, q);
        size_t ga = (size_t)(cy + r) * sA + ka + q * 8;
        size_t gb = (size_t)(cx + r) * sB + kt + q * 8;
        cp_async16(sstage + T_AHI + so, Ah + ga);
        cp_async16(sstage + T_ALO + so, Al + ga);
        cp_async16(sstage + T_BHI + so, Bh + gb);
        cp_async16(sstage + T_BLO + so, Bl + gb);
    }
}

__global__ __launch_bounds__(256, 2)
void gemm_uni(GP p0, GP p1, int n0) {
    extern __shared__ char smem[];
    const uint32_t sb = smem_u32(smem);
    int id = blockIdx.x;
    const GP* __restrict__ p;
    if (id < n0) p = &p0;
    else { p = &p1; id -= n0; }

    const int tid  = threadIdx.x;
    const int lane = tid & 31;
    const int wid  = tid >> 5;
    const int wm   = wid >> 2;
    const int wn   = wid & 3;
    const int cx   = (id % p->gx) * BN;
    const int cy   = (id / p->gx) * BM;
    const int NCK  = p->Kloop >> 5;

    float acc[4][4][4];
    #pragma unroll
    for (int i = 0; i < 4; i++)
        #pragma unroll
        for (int j = 0; j < 4; j++)
            #pragma unroll
            for (int k = 0; k < 4; k++) acc[i][j][k] = 0.0f;

    const int arow = wm * 64 + (lane & 15);
    const int abit = (lane >> 4) & 1;
    const int asw  = (arow >> 1) & 3;
    const int brow = wn * 32 + (lane & 7) + ((lane & 16) ? 8 : 0);
    const int bbit = (lane >> 3) & 1;
    const int bsw  = (brow >> 1) & 3;
    uint32_t aofk[2], bofk[2];
    #pragma unroll
    for (int ks = 0; ks < 2; ks++) {
        aofk[ks] = (uint32_t)(arow * 64 + ((((ks << 1) | abit) ^ asw) << 4));
        bofk[ks] = (uint32_t)(brow * 64 + ((((ks << 1) | bbit) ^ bsw) << 4));
    }

    // prefetch chunks 0,1
    #pragma unroll
    for (int c = 0; c < STAGES - 1; c++) {
        if (c < NCK)
            load_chunk(sb + c * STAGE_BYTES, p, c * BK, cy, cx, tid);
        cp_commit();
    }

    int bufc = 0;
    for (int c = 0; c < NCK; c++) {
        if (c == NCK - 1) cp_wait<0>(); else cp_wait<1>();
        // Single sync per chunk: orders (a) chunk-c data visible to all warps,
        // (b) all warps finished computing on buffer (c-1)%3 == (c+2)%3 before
        // any warp's cp.async below overwrites it.  (End-of-loop sync removed —
        // provably redundant given program order compute(c-1) -> this sync.)
        __syncthreads();
        if (c + 2 < NCK) {
            int nb = bufc + 2; if (nb >= STAGES) nb -= STAGES;
            load_chunk(sb + nb * STAGE_BYTES, p, (c + 2) * BK, cy, cx, tid);
            cp_commit();
        }

        const uint32_t st = sb + bufc * STAGE_BYTES;
        bufc++; if (bufc >= STAGES) bufc = 0;

        #pragma unroll
        for (int ks = 0; ks < 2; ks++) {
            // separate fragment arrays -> no WAR serialization between groups;
            // ptxas can hoist each group's ldsm behind the previous group's MMAs.
            uint32_t a_hi[4][4], a_lo[4][4], b_hi[4][2], b_lo[4][2];
            #pragma unroll
            for (int nf2 = 0; nf2 < 2; nf2++) {
                uint32_t r0, r1, r2, r3;
                ldsm_x4(st + T_BLO + bofk[ks] + nf2 * 1024, r0, r1, r2, r3);
                b_lo[nf2 * 2 + 0][0] = r0; b_lo[nf2 * 2 + 0][1] = r1;
                b_lo[nf2 * 2 + 1][0] = r2; b_lo[nf2 * 2 + 1][1] = r3;
            }
            #pragma unroll
            for (int mf = 0; mf < 4; mf++)
                ldsm_x4(st + T_AHI + aofk[ks] + mf * 1024,
                        a_hi[mf][0], a_hi[mf][1], a_hi[mf][2], a_hi[mf][3]);
            #pragma unroll
            for (int nf2 = 0; nf2 < 2; nf2++) {
                uint32_t r0, r1, r2, r3;
                ldsm_x4(st + T_BHI + bofk[ks] + nf2 * 1024, r0, r1, r2, r3);
                b_hi[nf2 * 2 + 0][0] = r0; b_hi[nf2 * 2 + 0][1] = r1;
                b_hi[nf2 * 2 + 1][0] = r2; b_hi[nf2 * 2 + 1][1] = r3;
            }
            // group 0: acc += Ahi * Blo
            #pragma unroll
            for (int mf = 0; mf < 4; mf++)
                #pragma unroll
                for (int nf = 0; nf < 4; nf++)
                    mma_bf16(acc[mf][nf], a_hi[mf], b_lo[nf]);
            // group 2's A frags fetched while group 1 computes
            #pragma unroll
            for (int mf = 0; mf < 4; mf++)
                ldsm_x4(st + T_ALO + aofk[ks] + mf * 1024,
                        a_lo[mf][0], a_lo[mf][1], a_lo[mf][2], a_lo[mf][3]);
            // group 1: acc += Ahi * Bhi
            #pragma unroll
            for (int mf = 0; mf < 4; mf++)
                #pragma unroll
                for (int nf = 0; nf < 4; nf++)
                    mma_bf16(acc[mf][nf], a_hi[mf], b_hi[nf]);
            // group 2: acc += Alo * Bhi
            #pragma unroll
            for (int mf = 0; mf < 4; mf++)
                #pragma unroll
                for (int nf = 0; nf < 4; nf++)
                    mma_bf16(acc[mf][nf], a_lo[mf], b_hi[nf]);
        }
    }

    // ---------------- epilogue -----------------------------------------------
    const int gid = lane >> 2;
    const int tig = lane & 3;
    const int ldC = p->ldC;
    const int biasmode = p->biasmode;
    const int relu = p->relu;
    const int split = p->split;
    #pragma unroll
    for (int mf = 0; mf < 4; mf++) {
        const int row0 = cy + wm * 64 + mf * 16 + gid;
        float rb0 = 0.f, rb1 = 0.f;
        if (biasmode == 2) { rb0 = p->bias[row0]; rb1 = p->bias[row0 + 8]; }
        #pragma unroll
        for (int nf = 0; nf < 4; nf++) {
            const int col = cx + wn * 32 + nf * 8 + tig * 2;
            float v0 = acc[mf][nf][0], v1 = acc[mf][nf][1];
            float v2 = acc[mf][nf][2], v3 = acc[mf][nf][3];
            if (biasmode == 1) {
                float b0 = p->bias[col], b1 = p->bias[col + 1];
                v0 += b0; v1 += b1; v2 += b0; v3 += b1;
            } else if (biasmode == 2) {
                v0 += rb0; v1 += rb0; v2 += rb1; v3 += rb1;
            }
            if (relu) {
                v0 = fmaxf(v0, 0.f); v1 = fmaxf(v1, 0.f);
                v2 = fmaxf(v2, 0.f); v3 = fmaxf(v3, 0.f);
            }
            if (!split) {
                *(float2*)(p->Cf + (size_t)row0 * ldC + col)       = make_float2(v0, v1);
                *(float2*)(p->Cf + (size_t)(row0 + 8) * ldC + col) = make_float2(v2, v3);
            } else {
                bf16 h0 = __float2bfloat16(v0), h1 = __float2bfloat16(v1);
                bf16 h2 = __float2bfloat16(v2), h3 = __float2bfloat16(v3);
                bf16 l0 = __float2bfloat16(v0 - __bfloat162float(h0));
                bf16 l1 = __float2bfloat16(v1 - __bfloat162float(h1));
                bf16 l2 = __float2bfloat16(v2 - __bfloat162float(h2));
                bf16 l3 = __float2bfloat16(v3 - __bfloat162float(h3));
                __nv_bfloat162 hp0; hp0.x = h0; hp0.y = h1;
                __nv_bfloat162 hp1; hp1.x = h2; hp1.y = h3;
                __nv_bfloat162 lp0; lp0.x = l0; lp0.y = l1;
                __nv_bfloat162 lp1; lp1.x = l2; lp1.y = l3;
                *(__nv_bfloat162*)(p->Chi + (size_t)row0 * ldC + col)       = hp0;
                *(__nv_bfloat162*)(p->Chi + (size_t)(row0 + 8) * ldC + col) = hp1;
                *(__nv_bfloat162*)(p->Clo + (size_t)row0 * ldC + col)       = lp0;
                *(__nv_bfloat162*)(p->Clo + (size_t)(row0 + 8) * ldC + col) = lp1;
            }
        }
    }
}

// ---------------- elementwise kernels -----------------------------------------
__global__ void pe_table_kernel(float* invden, float* colsum) {
    int k = blockIdx.x * blockDim.x + threadIdx.x;
    if (k < DD / 2)
        invden[k] = powf(10000.0f, -(float)(2 * k) / (float)DD);
    if (k < DD) colsum[k] = 0.0f;
}

#define CS_ROWS 128
__global__ void colsum_kernel(const float* __restrict__ X,
                              const float* __restrict__ invden,
                              float* __restrict__ colsum) {
    int j  = blockIdx.x * blockDim.x + threadIdx.x;
    int r0 = blockIdx.y * CS_ROWS;
    float inv = invden[j >> 1];
    bool odd = (j & 1);
    float s = 0.0f;
    #pragma unroll 4
    for (int i = 0; i < CS_ROWS; i++) {
        int pos = r0 + i;
        float arg = (float)pos * inv;
        float pe = odd ? cosf(arg) : sinf(arg);
        s += pe * X[(size_t)pos * DD + j];
    }
    atomicAdd(&colsum[j], s);
}

__device__ __forceinline__ void split_store(bf16* hi, bf16* lo, size_t idx, float v) {
    bf16 h = __float2bfloat16(v);
    hi[idx] = h;
    lo[idx] = __float2bfloat16(v - __bfloat162float(h));
}

__global__ void loo_split_kernel(const float* __restrict__ X,
                                 const float* __restrict__ invden,
                                 const float* __restrict__ colsum,
                                 bf16* __restrict__ lhi, bf16* __restrict__ llo,
                                 bf16* __restrict__ xhi, bf16* __restrict__ xlo) {
    int idx = blockIdx.x * blockDim.x + threadIdx.x;   // over N*D
    int row = idx >> 10;
    int j   = idx & 1023;
    float x = X[idx];
    split_store(xhi, xlo, idx, x);
    float arg = (float)row * invden[j >> 1];
    float pe  = (j & 1) ? cosf(arg) : sinf(arg);
    float v = (colsum[j] - pe * x) * (1.0f / (float)(NN - 1));
    split_store(lhi, llo, idx, v);
}

// merged transpose+split for the three weights; job ranges by blockIdx
#define TS_WV 1024
#define TS_W1 (TS_WV + 4096)
#define TS_W2 (TS_W1 + 8192)
__global__ void tsplit3_kernel(const float* __restrict__ Wv,
                               bf16* __restrict__ WvThi, bf16* __restrict__ WvTlo,
                               const float* __restrict__ W1,
                               bf16* __restrict__ W1Thi, bf16* __restrict__ W1Tlo,
                               const float* __restrict__ W2,
                               bf16* __restrict__ W2Thi, bf16* __restrict__ W2Tlo) {
    __shared__ float t[32][33];
    int id = blockIdx.x;
    const float* src;
    bf16 *dhi, *dlo;
    int R, C, nbx;
    if (id < TS_WV)      { src = Wv; dhi = WvThi; dlo = WvTlo; R = DD;     C = DD; nbx = DD / 32; }
    else if (id < TS_W1) { src = W1; dhi = W1Thi; dlo = W1Tlo; R = 2 * DD; C = HH; nbx = HH / 32; id -= TS_WV; }
    else                 { src = W2; dhi = W2Thi; dlo = W2Tlo; R = HH;     C = NN; nbx = NN / 32; id -= TS_W1; }
    int bx = (id % nbx) * 32;
    int by = (id / nbx) * 32;
    int tx = threadIdx.x, ty = threadIdx.y;
    #pragma unroll
    for (int i = 0; i < 4; i++)
        t[ty + i * 8][tx] = src[(size_t)(by + ty + i * 8) * C + bx + tx];
    __syncthreads();
    #pragma unroll
    for (int i = 0; i < 4; i++) {
        float v = t[tx][ty + i * 8];
        split_store(dhi, dlo, (size_t)(bx + ty + i * 8) * R + by + tx, v);
    }
}

// row softmax over scoresA+scoresB; writes att split bf16
__global__ void softmax_split_kernel(const float* __restrict__ SA,
                                     const float* __restrict__ SB,
                                     bf16* __restrict__ ahi, bf16* __restrict__ alo, int n) {
    __shared__ float red[8];
    __shared__ float buf[4096];
    const float* rowA = SA + (size_t)blockIdx.x * n;
    const float* rowB = SB + (size_t)blockIdx.x * n;
    int tid = threadIdx.x;
    int lane = tid & 31, warp = tid >> 5;

    float m = -1e30f;
    for (int j = tid; j < n; j += 256) {
        float v = rowA[j] + rowB[j];
        buf[j] = v;
        m = fmaxf(m, v);
    }
    #pragma unroll
    for (int o = 16; o > 0; o >>= 1) m = fmaxf(m, __shfl_xor_sync(0xffffffffu, m, o));
    if (lane == 0) red[warp] = m;
    __syncthreads();
    if (tid < 8) {
        float v = red[tid];
        #pragma unroll
        for (int o = 4; o > 0; o >>= 1) v = fmaxf(v, __shfl_xor_sync(0xffu, v, o));
        if (tid == 0) red[0] = v;
    }
    __syncthreads();
    m = red[0];
    __syncthreads();

    float s = 0.0f;
    for (int j = tid; j < n; j += 256) {
        float e = __expf(buf[j] - m);
        buf[j] = e;
        s += e;
    }
    #pragma unroll
    for (int o = 16; o > 0; o >>= 1) s += __shfl_xor_sync(0xffffffffu, s, o);
    if (lane == 0) red[warp] = s;
    __syncthreads();
    if (tid < 8) {
        float v = red[tid];
        #pragma unroll
        for (int o = 4; o > 0; o >>= 1) v += __shfl_xor_sync(0xffu, v, o);
        if (tid == 0) red[0] = v;
    }
    __syncthreads();
    float inv = 1.0f / red[0];
    size_t base = (size_t)blockIdx.x * n;
    for (int j = tid; j < n; j += 256) {
        float a = buf[j] * inv;
        split_store(ahi, alo, base + j, a);
    }
}

// ---------------- driver ------------------------------------------------------
extern "C" void kernel_launch(void* const* d_in, const int* in_sizes, int n_in,
                              void* d_out, int out_size) {
    const float* X  = (const float*)d_in[0];
    const float* Wv = (const float*)d_in[2];
    const float* bv = (const float*)d_in[3];
    const float* W1 = (const float*)d_in[4];
    const float* b1 = (const float*)d_in[5];
    const float* W2 = (const float*)d_in[6];
    const float* b2 = (const float*)d_in[7];
    float* out = (float*)d_out;

    void* p;
    cudaGetSymbolAddress(&p, g_invden);  float* invden  = (float*)p;
    cudaGetSymbolAddress(&p, g_colsum);  float* colsum  = (float*)p;
    cudaGetSymbolAddress(&p, g_scoresA); float* scoresA = (float*)p;
    cudaGetSymbolAddress(&p, g_scoresB); float* scoresB = (float*)p;
    cudaGetSymbolAddress(&p, g_Xhi);    bf16* Xhi   = (bf16*)p;
    cudaGetSymbolAddress(&p, g_Xlo);    bf16* Xlo   = (bf16*)p;
    cudaGetSymbolAddress(&p, g_loohi);  bf16* loohi = (bf16*)p;
    cudaGetSymbolAddress(&p, g_loolo);  bf16* loolo = (bf16*)p;
    cudaGetSymbolAddress(&p, g_WvThi);  bf16* WvThi = (bf16*)p;
    cudaGetSymbolAddress(&p, g_WvTlo);  bf16* WvTlo = (bf16*)p;
    cudaGetSymbolAddress(&p, g_W1Thi);  bf16* W1Thi = (bf16*)p;
    cudaGetSymbolAddress(&p, g_W1Tlo);  bf16* W1Tlo = (bf16*)p;
    cudaGetSymbolAddress(&p, g_hidhi);  bf16* hdhi  = (bf16*)p;
    cudaGetSymbolAddress(&p, g_hidlo);  bf16* hdlo  = (bf16*)p;
    cudaGetSymbolAddress(&p, g_W2Thi);  bf16* W2Thi = (bf16*)p;
    cudaGetSymbolAddress(&p, g_W2Tlo);  bf16* W2Tlo = (bf16*)p;
    cudaGetSymbolAddress(&p, g_atthi);  bf16* athi  = (bf16*)p;
    cudaGetSymbolAddress(&p, g_attlo);  bf16* atlo  = (bf16*)p;
    cudaGetSymbolAddress(&p, g_VThi);   bf16* VThi  = (bf16*)p;
    cudaGetSymbolAddress(&p, g_VTlo);   bf16* VTlo  = (bf16*)p;

    cudaFuncSetAttribute(gemm_uni, cudaFuncAttributeMaxDynamicSharedMemorySize, GSMEM);

    // --- operand prep --------------------------------------------------------
    pe_table_kernel<<<4, 256>>>(invden, colsum);
    colsum_kernel<<<dim3(DD / 256, NN / CS_ROWS), 256>>>(X, invden, colsum);
    loo_split_kernel<<<(NN * DD) / 256, 256>>>(X, invden, colsum, loohi, loolo, Xhi, Xlo);
    tsplit3_kernel<<<TS_W2, dim3(32, 8)>>>(Wv, WvThi, WvTlo, W1, W1Thi, W1Tlo, W2, W2Thi, W2Tlo);

    // --- job descriptions -----------------------------------------------------
    // G1: VT = WvT @ X^T + bv(row)  M=1024 N=4096 K=1024, split out
    GP g1;
    g1.Ahi = WvThi; g1.Alo = WvTlo; g1.A2hi = WvThi; g1.A2lo = WvTlo;
    g1.Bhi = Xhi;   g1.Blo = Xlo;
    g1.bias = bv;   g1.Cf = nullptr; g1.Chi = VThi; g1.Clo = VTlo;
    g1.gx = NN / BN;
    g1.ldA1 = DD; g1.ldA2 = DD; g1.ldB = DD; g1.ldC = NN;
    g1.Kloop = DD; g1.K1 = DD;
    g1.biasmode = 2; g1.relu = 0; g1.split = 1;
    // G2: hidden = relu([X|loo] @ W1T^T + b1)  M=4096 N=2048 K=2048 (K1=1024)
    GP g2;
    g2.Ahi = Xhi; g2.Alo = Xlo; g2.A2hi = loohi; g2.A2lo = loolo;
    g2.Bhi = W1Thi; g2.Blo = W1Tlo;
    g2.bias = b1; g2.Cf = nullptr; g2.Chi = hdhi; g2.Clo = hdlo;
    g2.gx = HH / BN;
    g2.ldA1 = DD; g2.ldA2 = DD; g2.ldB = 2 * DD; g2.ldC = HH;
    g2.Kloop = 2 * DD; g2.K1 = DD;
    g2.biasmode = 1; g2.relu = 1; g2.split = 1;
    // G3 split-K halves
    GP g3a;
    g3a.Ahi = hdhi; g3a.Alo = hdlo; g3a.A2hi = hdhi; g3a.A2lo = hdlo;
    g3a.Bhi = W2Thi; g3a.Blo = W2Tlo;
    g3a.bias = b2; g3a.Cf = scoresA; g3a.Chi = nullptr; g3a.Clo = nullptr;
    g3a.gx = NN / BN;
    g3a.ldA1 = HH; g3a.ldA2 = HH; g3a.ldB = HH; g3a.ldC = NN;
    g3a.Kloop = HH / 2; g3a.K1 = HH / 2;
    g3a.biasmode = 1; g3a.relu = 0; g3a.split = 0;
    GP g3b = g3a;
    g3b.Ahi = hdhi + HH / 2;  g3b.Alo = hdlo + HH / 2;
    g3b.A2hi = g3b.Ahi;       g3b.A2lo = g3b.Alo;
    g3b.Bhi = W2Thi + HH / 2; g3b.Blo = W2Tlo + HH / 2;
    g3b.Cf = scoresB;
    g3b.biasmode = 0;
    // G4: out = att @ V  M=4096 N=1024 K=4096
    GP g4;
    g4.Ahi = athi; g4.Alo = atlo; g4.A2hi = athi; g4.A2lo = atlo;
    g4.Bhi = VThi; g4.Blo = VTlo;
    g4.bias = nullptr; g4.Cf = out; g4.Chi = nullptr; g4.Clo = nullptr;
    g4.gx = DD / BN;
    g4.ldA1 = NN; g4.ldA2 = NN; g4.ldB = NN; g4.ldC = DD;
    g4.Kloop = NN; g4.K1 = NN;
    g4.biasmode = 0; g4.relu = 0; g4.split = 0;

    // --- schedule (longest-job-first within each launch) ----------------------
    // Stage A: G2 (64-chunk CTAs, 512) FIRST, then G1 (32-chunk, 256)
    {
        int n2 = g2.gx * (NN / BM);                      // 512
        int n1 = g1.gx * (DD / BM);                      // 256
        gemm_uni<<<n2 + n1, 256, GSMEM>>>(g2, g1, n2);
    }
    // Stage B: split-K G3 (uniform 32-chunk, 2048)
    {
        int n3 = (NN / BN) * (NN / BM);                  // 1024 each
        gemm_uni<<<2 * n3, 256, GSMEM>>>(g3a, g3b, n3);
    }
    // softmax -> att split
    softmax_split_kernel<<<NN, 256>>>(scoresA, scoresB, athi, atlo, NN);
    // Stage C: G4
    {
        int n4 = g4.gx * (NN / BM);                      // 256
        gemm_uni<<<n4, 256, GSMEM>>>(g4, g4, n4);
    }
}

// round 14
// speedup vs baseline: 1.0271x; 1.0271x over previous
#include <cuda_runtime.h>
#include <cuda_bf16.h>
#include <math.h>
#include <stdint.h>

// Problem constants
#define NN 4096
#define DD 1024
#define HH 2048

typedef __nv_bfloat16 bf16;

// ---------------- scratch (device globals; no allocations allowed) ----------
__device__ float g_colsum[DD];
__device__ float g_scoresA[(size_t)NN * NN];           // 64 MB
__device__ float g_scoresB[(size_t)NN * NN];           // 64 MB

__device__ bf16 g_Xhi[(size_t)NN * DD],     g_Xlo[(size_t)NN * DD];
__device__ bf16 g_loohi[(size_t)NN * DD],   g_loolo[(size_t)NN * DD];
__device__ bf16 g_WvThi[(size_t)DD * DD],   g_WvTlo[(size_t)DD * DD];
__device__ bf16 g_W1Thi[(size_t)HH * 2*DD], g_W1Tlo[(size_t)HH * 2*DD];
__device__ bf16 g_hidhi[(size_t)NN * HH],   g_hidlo[(size_t)NN * HH];
__device__ bf16 g_W2Thi[(size_t)NN * HH],   g_W2Tlo[(size_t)NN * HH];
__device__ bf16 g_atthi[(size_t)NN * NN],   g_attlo[(size_t)NN * NN];
__device__ bf16 g_VThi[(size_t)DD * NN],    g_VTlo[(size_t)DD * NN];

// ---------------- helpers -----------------------------------------------------
__device__ __forceinline__ uint32_t smem_u32(const void* p) {
    uint32_t a;
    asm("{ .reg .u64 t; cvta.to.shared.u64 t, %1; cvt.u32.u64 %0, t; }" : "=r"(a) : "l"(p));
    return a;
}
__device__ __forceinline__ void cp_async16(uint32_t saddr, const void* gaddr) {
    asm volatile("cp.async.cg.shared.global [%0], [%1], 16;" :: "r"(saddr), "l"(gaddr));
}
__device__ __forceinline__ void cp_commit() {
    asm volatile("cp.async.commit_group;");
}
template<int N>
__device__ __forceinline__ void cp_wait() {
    asm volatile("cp.async.wait_group %0;" :: "n"(N));
}
__device__ __forceinline__ void ldsm_x4(uint32_t addr, uint32_t& r0, uint32_t& r1,
                                        uint32_t& r2, uint32_t& r3) {
    asm volatile("ldmatrix.sync.aligned.m8n8.x4.shared.b16 {%0,%1,%2,%3}, [%4];"
                 : "=r"(r0), "=r"(r1), "=r"(r2), "=r"(r3) : "r"(addr));
}
__device__ __forceinline__ void mma_bf16(float* c, const uint32_t* a, const uint32_t* b) {
    asm volatile(
        "mma.sync.aligned.m16n8k16.row.col.f32.bf16.bf16.f32 "
        "{%0,%1,%2,%3}, {%4,%5,%6,%7}, {%8,%9}, {%0,%1,%2,%3};"
        : "+f"(c[0]), "+f"(c[1]), "+f"(c[2]), "+f"(c[3])
        : "r"(a[0]), "r"(a[1]), "r"(a[2]), "r"(a[3]), "r"(b[0]), "r"(b[1]));
}

// ---------------- unified GEMM job description --------------------------------
struct GP {
    const bf16 *Ahi, *Alo, *A2hi, *A2lo;   // A row-major [M][ldA]; A2 for k>=K1
    const bf16 *Bhi, *Blo;                 // B' row-major [N][ldB]
    const float* bias;
    float* Cf;
    bf16 *Chi, *Clo;
    int gx;                                // tiles along N
    int ldA1, ldA2, ldB, ldC;
    int Kloop, K1;
    int biasmode;                          // 0 none, 1 per-col, 2 per-row
    int relu, split;
};

#define BM 128
#define BN 128
#define BK 32
#define TILE (BM * 64)               // 8192 B
#define T_AHI 0
#define T_ALO TILE
#define T_BHI (2 * TILE)
#define T_BLO (3 * TILE)
#define STAGE_BYTES (4 * TILE)       // 32768 B
#define STAGES 3
#define GSMEM (STAGES * STAGE_BYTES) // 98304 B

__device__ __forceinline__ uint32_t swz(int r, int q) {
    return (uint32_t)(r * 64 + ((q ^ ((r >> 1) & 3)) << 4));
}

__device__ __forceinline__ void load_chunk(uint32_t sstage, const GP* __restrict__ p,
                                           int kt, int cy, int cx, int tid) {
    const bf16 *Ah, *Al;
    int ka, sA;
    if (kt < p->K1) { Ah = p->Ahi;  Al = p->Alo;  ka = kt;         sA = p->ldA1; }
    else            { Ah = p->A2hi; Al = p->A2lo; ka = kt - p->K1; sA = p->ldA2; }
    const bf16* Bh = p->Bhi;
    const bf16* Bl = p->Blo;
    const int sB = p->ldB;
    #pragma unroll
    for (int i = 0; i < 2; i++) {
        int u = tid + i * 256;       // 0..511
        int r = u >> 2, q = u & 3;
        uint32_t so = swz(r, q);
        size_t ga = (size_t)(cy + r) * sA + ka + q * 8;
        size_t gb = (size_t)(cx + r) * sB + kt + q * 8;
        cp_async16(sstage + T_AHI + so, Ah + ga);
        cp_async16(sstage + T_ALO + so, Al + ga);
        cp_async16(sstage + T_BHI + so, Bh + gb);
        cp_async16(sstage + T_BLO + so, Bl + gb);
    }
}

__global__ __launch_bounds__(256, 2)
void gemm_uni(GP p0, GP p1, int n0) {
    extern __shared__ char smem[];
    const uint32_t sb = smem_u32(smem);
    int id = blockIdx.x;
    const GP* __restrict__ p;
    if (id < n0) p = &p0;
    else { p = &p1; id -= n0; }

    const int tid  = threadIdx.x;
    const int lane = tid & 31;
    const int wid  = tid >> 5;
    const int wm   = wid >> 2;
    const int wn   = wid & 3;
    const int cx   = (id % p->gx) * BN;
    const int cy   = (id / p->gx) * BM;
    const int NCK  = p->Kloop >> 5;

    float acc[4][4][4];
    #pragma unroll
    for (int i = 0; i < 4; i++)
        #pragma unroll
        for (int j = 0; j < 4; j++)
            #pragma unroll
            for (int k = 0; k < 4; k++) acc[i][j][k] = 0.0f;

    const int arow = wm * 64 + (lane & 15);
    const int abit = (lane >> 4) & 1;
    const int asw  = (arow >> 1) & 3;
    const int brow = wn * 32 + (lane & 7) + ((lane & 16) ? 8 : 0);
    const int bbit = (lane >> 3) & 1;
    const int bsw  = (brow >> 1) & 3;
    uint32_t aofk[2], bofk[2];
    #pragma unroll
    for (int ks = 0; ks < 2; ks++) {
        aofk[ks] = (uint32_t)(arow * 64 + ((((ks << 1) | abit) ^ asw) << 4));
        bofk[ks] = (uint32_t)(brow * 64 + ((((ks << 1) | bbit) ^ bsw) << 4));
    }

    // prefetch chunks 0,1
    #pragma unroll
    for (int c = 0; c < STAGES - 1; c++) {
        if (c < NCK)
            load_chunk(sb + c * STAGE_BYTES, p, c * BK, cy, cx, tid);
        cp_commit();
    }

    int bufc = 0;
    for (int c = 0; c < NCK; c++) {
        if (c == NCK - 1) cp_wait<0>(); else cp_wait<1>();
        __syncthreads();
        if (c + 2 < NCK) {
            int nb = bufc + 2; if (nb >= STAGES) nb -= STAGES;
            load_chunk(sb + nb * STAGE_BYTES, p, (c + 2) * BK, cy, cx, tid);
            cp_commit();
        }

        const uint32_t st = sb + bufc * STAGE_BYTES;
        bufc++; if (bufc >= STAGES) bufc = 0;

        #pragma unroll
        for (int ks = 0; ks < 2; ks++) {
            uint32_t a[4][4], b[4][2];
            // acc += Ahi*Blo
            #pragma unroll
            for (int nf2 = 0; nf2 < 2; nf2++) {
                uint32_t r0, r1, r2, r3;
                ldsm_x4(st + T_BLO + bofk[ks] + nf2 * 1024, r0, r1, r2, r3);
                b[nf2 * 2 + 0][0] = r0; b[nf2 * 2 + 0][1] = r1;
                b[nf2 * 2 + 1][0] = r2; b[nf2 * 2 + 1][1] = r3;
            }
            #pragma unroll
            for (int mf = 0; mf < 4; mf++)
                ldsm_x4(st + T_AHI + aofk[ks] + mf * 1024,
                        a[mf][0], a[mf][1], a[mf][2], a[mf][3]);
            #pragma unroll
            for (int mf = 0; mf < 4; mf++)
                #pragma unroll
                for (int nf = 0; nf < 4; nf++)
                    mma_bf16(acc[mf][nf], a[mf], b[nf]);
            // acc += Ahi*Bhi
            #pragma unroll
            for (int nf2 = 0; nf2 < 2; nf2++) {
                uint32_t r0, r1, r2, r3;
                ldsm_x4(st + T_BHI + bofk[ks] + nf2 * 1024, r0, r1, r2, r3);
                b[nf2 * 2 + 0][0] = r0; b[nf2 * 2 + 0][1] = r1;
                b[nf2 * 2 + 1][0] = r2; b[nf2 * 2 + 1][1] = r3;
            }
            #pragma unroll
            for (int mf = 0; mf < 4; mf++)
                #pragma unroll
                for (int nf = 0; nf < 4; nf++)
                    mma_bf16(acc[mf][nf], a[mf], b[nf]);
            // acc += Alo*Bhi
            #pragma unroll
            for (int mf = 0; mf < 4; mf++)
                ldsm_x4(st + T_ALO + aofk[ks] + mf * 1024,
                        a[mf][0], a[mf][1], a[mf][2], a[mf][3]);
            #pragma unroll
            for (int mf = 0; mf < 4; mf++)
                #pragma unroll
                for (int nf = 0; nf < 4; nf++)
                    mma_bf16(acc[mf][nf], a[mf], b[nf]);
        }
        __syncthreads();
    }

    // ---------------- epilogue -----------------------------------------------
    const int gid = lane >> 2;
    const int tig = lane & 3;
    const int ldC = p->ldC;
    const int biasmode = p->biasmode;
    const int relu = p->relu;
    const int split = p->split;
    #pragma unroll
    for (int mf = 0; mf < 4; mf++) {
        const int row0 = cy + wm * 64 + mf * 16 + gid;
        float rb0 = 0.f, rb1 = 0.f;
        if (biasmode == 2) { rb0 = p->bias[row0]; rb1 = p->bias[row0 + 8]; }
        #pragma unroll
        for (int nf = 0; nf < 4; nf++) {
            const int col = cx + wn * 32 + nf * 8 + tig * 2;
            float v0 = acc[mf][nf][0], v1 = acc[mf][nf][1];
            float v2 = acc[mf][nf][2], v3 = acc[mf][nf][3];
            if (biasmode == 1) {
                float b0 = p->bias[col], b1 = p->bias[col + 1];
                v0 += b0; v1 += b1; v2 += b0; v3 += b1;
            } else if (biasmode == 2) {
                v0 += rb0; v1 += rb0; v2 += rb1; v3 += rb1;
            }
            if (relu) {
                v0 = fmaxf(v0, 0.f); v1 = fmaxf(v1, 0.f);
                v2 = fmaxf(v2, 0.f); v3 = fmaxf(v3, 0.f);
            }
            if (!split) {
                *(float2*)(p->Cf + (size_t)row0 * ldC + col)       = make_float2(v0, v1);
                *(float2*)(p->Cf + (size_t)(row0 + 8) * ldC + col) = make_float2(v2, v3);
            } else {
                bf16 h0 = __float2bfloat16(v0), h1 = __float2bfloat16(v1);
                bf16 h2 = __float2bfloat16(v2), h3 = __float2bfloat16(v3);
                bf16 l0 = __float2bfloat16(v0 - __bfloat162float(h0));
                bf16 l1 = __float2bfloat16(v1 - __bfloat162float(h1));
                bf16 l2 = __float2bfloat16(v2 - __bfloat162float(h2));
                bf16 l3 = __float2bfloat16(v3 - __bfloat162float(h3));
                __nv_bfloat162 hp0; hp0.x = h0; hp0.y = h1;
                __nv_bfloat162 hp1; hp1.x = h2; hp1.y = h3;
                __nv_bfloat162 lp0; lp0.x = l0; lp0.y = l1;
                __nv_bfloat162 lp1; lp1.x = l2; lp1.y = l3;
                *(__nv_bfloat162*)(p->Chi + (size_t)row0 * ldC + col)       = hp0;
                *(__nv_bfloat162*)(p->Chi + (size_t)(row0 + 8) * ldC + col) = hp1;
                *(__nv_bfloat162*)(p->Clo + (size_t)row0 * ldC + col)       = lp0;
                *(__nv_bfloat162*)(p->Clo + (size_t)(row0 + 8) * ldC + col) = lp1;
            }
        }
    }
}

// ---------------- elementwise kernels -----------------------------------------
__global__ void zero_kernel(float* p, int n) {
    int i = blockIdx.x * blockDim.x + threadIdx.x;
    if (i < n) p[i] = 0.0f;
}

__device__ __forceinline__ void split_store(bf16* hi, bf16* lo, size_t idx, float v) {
    bf16 h = __float2bfloat16(v);
    hi[idx] = h;
    lo[idx] = __float2bfloat16(v - __bfloat162float(h));
}

__device__ __forceinline__ __nv_bfloat162 pack_hi2(float a, float b) {
    __nv_bfloat162 r; r.x = __float2bfloat16(a); r.y = __float2bfloat16(b); return r;
}
__device__ __forceinline__ __nv_bfloat162 pack_lo2(float a, float b, __nv_bfloat162 h) {
    __nv_bfloat162 r;
    r.x = __float2bfloat16(a - __bfloat162float(h.x));
    r.y = __float2bfloat16(b - __bfloat162float(h.y));
    return r;
}

// -------- merged prep: colsum blocks (first) + weight transpose-splits --------
// colsum: 128 blocks.  Wv: 1024, W1: 4096, W2: 8192 tsplit blocks.
#define CS_ROWS 128
#define PR_CS   128
#define PR_WV   (PR_CS + 1024)
#define PR_W1   (PR_WV + 4096)
#define PR_W2   (PR_W1 + 8192)
__global__ void prep1_kernel(const float* __restrict__ X, float* __restrict__ colsum,
                             const float* __restrict__ Wv,
                             bf16* __restrict__ WvThi, bf16* __restrict__ WvTlo,
                             const float* __restrict__ W1,
                             bf16* __restrict__ W1Thi, bf16* __restrict__ W1Tlo,
                             const float* __restrict__ W2,
                             bf16* __restrict__ W2Thi, bf16* __restrict__ W2Tlo) {
    __shared__ float t[32][33];
    int id  = blockIdx.x;
    int tid = threadIdx.x;

    if (id < PR_CS) {
        // colsum partial: block handles 256 columns x 128 rows
        int j  = (id & 3) * 256 + tid;
        int r0 = (id >> 2) * CS_ROWS;
        float inv = powf(10000.0f, -(float)(j & ~1) / (float)DD);
        bool odd = (j & 1);
        float s = 0.0f;
        #pragma unroll 4
        for (int i = 0; i < CS_ROWS; i++) {
            int pos = r0 + i;
            float arg = (float)pos * inv;
            float pe = odd ? cosf(arg) : sinf(arg);
            s += pe * X[(size_t)pos * DD + j];
        }
        atomicAdd(&colsum[j], s);
        return;
    }

    const float* src;
    bf16 *dhi, *dlo;
    int R, C, nbx;
    if (id < PR_WV)      { src = Wv; dhi = WvThi; dlo = WvTlo; R = DD;     C = DD; nbx = DD / 32; id -= PR_CS; }
    else if (id < PR_W1) { src = W1; dhi = W1Thi; dlo = W1Tlo; R = 2 * DD; C = HH; nbx = HH / 32; id -= PR_WV; }
    else                 { src = W2; dhi = W2Thi; dlo = W2Tlo; R = HH;     C = NN; nbx = NN / 32; id -= PR_W1; }
    int bx = (id % nbx) * 32;
    int by = (id / nbx) * 32;
    int tx = tid & 31, ty = tid >> 5;
    #pragma unroll
    for (int i = 0; i < 4; i++)
        t[ty + i * 8][tx] = src[(size_t)(by + ty + i * 8) * C + bx + tx];
    __syncthreads();
    #pragma unroll
    for (int i = 0; i < 4; i++) {
        float v = t[tx][ty + i * 8];
        split_store(dhi, dlo, (size_t)(bx + ty + i * 8) * R + by + tx, v);
    }
}

// loo + X split, 2 elements per thread (even/odd pair shares one PE argument)
__global__ void loo_split_kernel(const float* __restrict__ X,
                                 const float* __restrict__ colsum,
                                 bf16* __restrict__ lhi, bf16* __restrict__ llo,
                                 bf16* __restrict__ xhi, bf16* __restrict__ xlo) {
    size_t idx2 = ((size_t)blockIdx.x * blockDim.x + threadIdx.x) * 2;
    int row = (int)(idx2 >> 10);
    int j   = (int)(idx2 & 1023);            // even
    float2 x2 = *(const float2*)(X + idx2);
    float inv = powf(10000.0f, -(float)j / (float)DD);
    float sv, cv;
    sincosf((float)row * inv, &sv, &cv);
    const float r1 = 1.0f / (float)(NN - 1);
    float l0 = (colsum[j]     - sv * x2.x) * r1;
    float l1 = (colsum[j + 1] - cv * x2.y) * r1;
    __nv_bfloat162 xh = pack_hi2(x2.x, x2.y);
    __nv_bfloat162 xl = pack_lo2(x2.x, x2.y, xh);
    __nv_bfloat162 lh = pack_hi2(l0, l1);
    __nv_bfloat162 ll = pack_lo2(l0, l1, lh);
    *(__nv_bfloat162*)(xhi + idx2) = xh;
    *(__nv_bfloat162*)(xlo + idx2) = xl;
    *(__nv_bfloat162*)(lhi + idx2) = lh;
    *(__nv_bfloat162*)(llo + idx2) = ll;
}

// row softmax over scoresA+scoresB; vectorized I/O; writes att split bf16
__global__ void softmax_split_kernel(const float* __restrict__ SA,
                                     const float* __restrict__ SB,
                                     bf16* __restrict__ ahi, bf16* __restrict__ alo, int n) {
    __shared__ float red[8];
    __shared__ float buf[4096];
    const float* rowA = SA + (size_t)blockIdx.x * n;
    const float* rowB = SB + (size_t)blockIdx.x * n;
    int tid = threadIdx.x;
    int lane = tid & 31, warp = tid >> 5;

    float m = -1e30f;
    for (int j = tid * 2; j < n; j += 512) {
        float2 a = *(const float2*)(rowA + j);
        float2 b = *(const float2*)(rowB + j);
        float v0 = a.x + b.x, v1 = a.y + b.y;
        buf[j] = v0; buf[j + 1] = v1;
        m = fmaxf(m, fmaxf(v0, v1));
    }
    #pragma unroll
    for (int o = 16; o > 0; o >>= 1) m = fmaxf(m, __shfl_xor_sync(0xffffffffu, m, o));
    if (lane == 0) red[warp] = m;
    __syncthreads();
    if (tid < 8) {
        float v = red[tid];
        #pragma unroll
        for (int o = 4; o > 0; o >>= 1) v = fmaxf(v, __shfl_xor_sync(0xffu, v, o));
        if (tid == 0) red[0] = v;
    }
    __syncthreads();
    m = red[0];
    __syncthreads();

    float s = 0.0f;
    for (int j = tid * 2; j < n; j += 512) {
        float e0 = __expf(buf[j] - m);
        float e1 = __expf(buf[j + 1] - m);
        buf[j] = e0; buf[j + 1] = e1;
        s += e0 + e1;
    }
    #pragma unroll
    for (int o = 16; o > 0; o >>= 1) s += __shfl_xor_sync(0xffffffffu, s, o);
    if (lane == 0) red[warp] = s;
    __syncthreads();
    if (tid < 8) {
        float v = red[tid];
        #pragma unroll
        for (int o = 4; o > 0; o >>= 1) v += __shfl_xor_sync(0xffu, v, o);
        if (tid == 0) red[0] = v;
    }
    __syncthreads();
    float inv = 1.0f / red[0];
    size_t base = (size_t)blockIdx.x * n;
    for (int j = tid * 2; j < n; j += 512) {
        float a0 = buf[j] * inv;
        float a1 = buf[j + 1] * inv;
        __nv_bfloat162 h = pack_hi2(a0, a1);
        __nv_bfloat162 l = pack_lo2(a0, a1, h);
        *(__nv_bfloat162*)(ahi + base + j) = h;
        *(__nv_bfloat162*)(alo + base + j) = l;
    }
}

// ---------------- driver ------------------------------------------------------
extern "C" void kernel_launch(void* const* d_in, const int* in_sizes, int n_in,
                              void* d_out, int out_size) {
    const float* X  = (const float*)d_in[0];
    const float* Wv = (const float*)d_in[2];
    const float* bv = (const float*)d_in[3];
    const float* W1 = (const float*)d_in[4];
    const float* b1 = (const float*)d_in[5];
    const float* W2 = (const float*)d_in[6];
    const float* b2 = (const float*)d_in[7];
    float* out = (float*)d_out;

    void* p;
    cudaGetSymbolAddress(&p, g_colsum);  float* colsum  = (float*)p;
    cudaGetSymbolAddress(&p, g_scoresA); float* scoresA = (float*)p;
    cudaGetSymbolAddress(&p, g_scoresB); float* scoresB = (float*)p;
    cudaGetSymbolAddress(&p, g_Xhi);    bf16* Xhi   = (bf16*)p;
    cudaGetSymbolAddress(&p, g_Xlo);    bf16* Xlo   = (bf16*)p;
    cudaGetSymbolAddress(&p, g_loohi);  bf16* loohi = (bf16*)p;
    cudaGetSymbolAddress(&p, g_loolo);  bf16* loolo = (bf16*)p;
    cudaGetSymbolAddress(&p, g_WvThi);  bf16* WvThi = (bf16*)p;
    cudaGetSymbolAddress(&p, g_WvTlo);  bf16* WvTlo = (bf16*)p;
    cudaGetSymbolAddress(&p, g_W1Thi);  bf16* W1Thi = (bf16*)p;
    cudaGetSymbolAddress(&p, g_W1Tlo);  bf16* W1Tlo = (bf16*)p;
    cudaGetSymbolAddress(&p, g_hidhi);  bf16* hdhi  = (bf16*)p;
    cudaGetSymbolAddress(&p, g_hidlo);  bf16* hdlo  = (bf16*)p;
    cudaGetSymbolAddress(&p, g_W2Thi);  bf16* W2Thi = (bf16*)p;
    cudaGetSymbolAddress(&p, g_W2Tlo);  bf16* W2Tlo = (bf16*)p;
    cudaGetSymbolAddress(&p, g_atthi);  bf16* athi  = (bf16*)p;
    cudaGetSymbolAddress(&p, g_attlo);  bf16* atlo  = (bf16*)p;
    cudaGetSymbolAddress(&p, g_VThi);   bf16* VThi  = (bf16*)p;
    cudaGetSymbolAddress(&p, g_VTlo);   bf16* VTlo  = (bf16*)p;

    cudaFuncSetAttribute(gemm_uni, cudaFuncAttributeMaxDynamicSharedMemorySize, GSMEM);

    // --- operand prep --------------------------------------------------------
    zero_kernel<<<4, 256>>>(colsum, DD);
    prep1_kernel<<<PR_W2, 256>>>(X, colsum, Wv, WvThi, WvTlo, W1, W1Thi, W1Tlo, W2, W2Thi, W2Tlo);
    loo_split_kernel<<<(NN * DD / 2) / 256, 256>>>(X, colsum, loohi, loolo, Xhi, Xlo);

    // --- job descriptions -----------------------------------------------------
    // G1: VT = WvT @ X^T + bv(row)  M=1024 N=4096 K=1024, split out
    GP g1;
    g1.Ahi = WvThi; g1.Alo = WvTlo; g1.A2hi = WvThi; g1.A2lo = WvTlo;
    g1.Bhi = Xhi;   g1.Blo = Xlo;
    g1.bias = bv;   g1.Cf = nullptr; g1.Chi = VThi; g1.Clo = VTlo;
    g1.gx = NN / BN;
    g1.ldA1 = DD; g1.ldA2 = DD; g1.ldB = DD; g1.ldC = NN;
    g1.Kloop = DD; g1.K1 = DD;
    g1.biasmode = 2; g1.relu = 0; g1.split = 1;
    // G2: hidden = relu([X|loo] @ W1T^T + b1)  M=4096 N=2048 K=2048 (K1=1024)
    GP g2;
    g2.Ahi = Xhi; g2.Alo = Xlo; g2.A2hi = loohi; g2.A2lo = loolo;
    g2.Bhi = W1Thi; g2.Blo = W1Tlo;
    g2.bias = b1; g2.Cf = nullptr; g2.Chi = hdhi; g2.Clo = hdlo;
    g2.gx = HH / BN;
    g2.ldA1 = DD; g2.ldA2 = DD; g2.ldB = 2 * DD; g2.ldC = HH;
    g2.Kloop = 2 * DD; g2.K1 = DD;
    g2.biasmode = 1; g2.relu = 1; g2.split = 1;
    // G3 split-K halves
    GP g3a;
    g3a.Ahi = hdhi; g3a.Alo = hdlo; g3a.A2hi = hdhi; g3a.A2lo = hdlo;
    g3a.Bhi = W2Thi; g3a.Blo = W2Tlo;
    g3a.bias = b2; g3a.Cf = scoresA; g3a.Chi = nullptr; g3a.Clo = nullptr;
    g3a.gx = NN / BN;
    g3a.ldA1 = HH; g3a.ldA2 = HH; g3a.ldB = HH; g3a.ldC = NN;
    g3a.Kloop = HH / 2; g3a.K1 = HH / 2;
    g3a.biasmode = 1; g3a.relu = 0; g3a.split = 0;
    GP g3b = g3a;
    g3b.Ahi = hdhi + HH / 2;  g3b.Alo = hdlo + HH / 2;
    g3b.A2hi = g3b.Ahi;       g3b.A2lo = g3b.Alo;
    g3b.Bhi = W2Thi + HH / 2; g3b.Blo = W2Tlo + HH / 2;
    g3b.Cf = scoresB;
    g3b.biasmode = 0;
    // G4: out = att @ V  M=4096 N=1024 K=4096
    GP g4;
    g4.Ahi = athi; g4.Alo = atlo; g4.A2hi = athi; g4.A2lo = atlo;
    g4.Bhi = VThi; g4.Blo = VTlo;
    g4.bias = nullptr; g4.Cf = out; g4.Chi = nullptr; g4.Clo = nullptr;
    g4.gx = DD / BN;
    g4.ldA1 = NN; g4.ldA2 = NN; g4.ldB = NN; g4.ldC = DD;
    g4.Kloop = NN; g4.K1 = NN;
    g4.biasmode = 0; g4.relu = 0; g4.split = 0;

    // --- schedule (longest-job-first within each launch) ----------------------
    // Stage A: G2 (64-chunk CTAs, 512) FIRST, then G1 (32-chunk, 256)
    {
        int n2 = g2.gx * (NN / BM);                      // 512
        int n1 = g1.gx * (DD / BM);                      // 256
        gemm_uni<<<n2 + n1, 256, GSMEM>>>(g2, g1, n2);
    }
    // Stage B: split-K G3 (uniform 32-chunk, 2048)
    {
        int n3 = (NN / BN) * (NN / BM);                  // 1024 each
        gemm_uni<<<2 * n3, 256, GSMEM>>>(g3a, g3b, n3);
    }
    // softmax -> att split
    softmax_split_kernel<<<NN, 256>>>(scoresA, scoresB, athi, atlo, NN);
    // Stage C: G4
    {
        int n4 = g4.gx * (NN / BM);                      // 256
        gemm_uni<<<n4, 256, GSMEM>>>(g4, g4, n4);
    }
}

// round 15
// speedup vs baseline: 1.0307x; 1.0035x over previous
#include <cuda_runtime.h>
#include <cuda_bf16.h>
#include <math.h>
#include <stdint.h>

// Problem constants
#define NN 4096
#define DD 1024
#define HH 2048

typedef __nv_bfloat16 bf16;

// ---------------- scratch (device globals; no allocations allowed) ----------
__device__ float g_colsum[DD];
__device__ float g_scoresA[(size_t)NN * NN];           // 64 MB
__device__ float g_scoresB[(size_t)NN * NN];           // 64 MB

__device__ bf16 g_Xhi[(size_t)NN * DD],     g_Xlo[(size_t)NN * DD];
__device__ bf16 g_loohi[(size_t)NN * DD],   g_loolo[(size_t)NN * DD];
__device__ bf16 g_WvThi[(size_t)DD * DD],   g_WvTlo[(size_t)DD * DD];
__device__ bf16 g_W1Thi[(size_t)HH * 2*DD], g_W1Tlo[(size_t)HH * 2*DD];
__device__ bf16 g_hidhi[(size_t)NN * HH],   g_hidlo[(size_t)NN * HH];
__device__ bf16 g_W2Thi[(size_t)NN * HH],   g_W2Tlo[(size_t)NN * HH];
__device__ bf16 g_atthi[(size_t)NN * NN],   g_attlo[(size_t)NN * NN];
__device__ bf16 g_VThi[(size_t)DD * NN],    g_VTlo[(size_t)DD * NN];

// ---------------- helpers -----------------------------------------------------
__device__ __forceinline__ uint32_t smem_u32(const void* p) {
    uint32_t a;
    asm("{ .reg .u64 t; cvta.to.shared.u64 t, %1; cvt.u32.u64 %0, t; }" : "=r"(a) : "l"(p));
    return a;
}
__device__ __forceinline__ void cp_async16(uint32_t saddr, const void* gaddr) {
    asm volatile("cp.async.cg.shared.global [%0], [%1], 16;" :: "r"(saddr), "l"(gaddr));
}
__device__ __forceinline__ void cp_commit() {
    asm volatile("cp.async.commit_group;");
}
template<int N>
__device__ __forceinline__ void cp_wait() {
    asm volatile("cp.async.wait_group %0;" :: "n"(N));
}
__device__ __forceinline__ void ldsm_x4(uint32_t addr, uint32_t& r0, uint32_t& r1,
                                        uint32_t& r2, uint32_t& r3) {
    asm volatile("ldmatrix.sync.aligned.m8n8.x4.shared.b16 {%0,%1,%2,%3}, [%4];"
                 : "=r"(r0), "=r"(r1), "=r"(r2), "=r"(r3) : "r"(addr));
}
__device__ __forceinline__ void mma_bf16(float* c, const uint32_t* a, const uint32_t* b) {
    asm volatile(
        "mma.sync.aligned.m16n8k16.row.col.f32.bf16.bf16.f32 "
        "{%0,%1,%2,%3}, {%4,%5,%6,%7}, {%8,%9}, {%0,%1,%2,%3};"
        : "+f"(c[0]), "+f"(c[1]), "+f"(c[2]), "+f"(c[3])
        : "r"(a[0]), "r"(a[1]), "r"(a[2]), "r"(a[3]), "r"(b[0]), "r"(b[1]));
}

// ---------------- unified GEMM job description --------------------------------
struct GP {
    const bf16 *Ahi, *Alo, *A2hi, *A2lo;   // A row-major [M][ldA]; A2 for k>=K1
    const bf16 *Bhi, *Blo;                 // B' row-major [N][ldB]
    const float* bias;
    float* Cf;
    bf16 *Chi, *Clo;
    int gx;                                // tiles along N
    int ldA1, ldA2, ldB, ldC;
    int Kloop, K1;
    int biasmode;                          // 0 none, 1 per-col, 2 per-row
    int relu, split;
};

#define BM 128
#define BN 128
#define BK 32
#define TILE (BM * 64)               // 8192 B
#define T_AHI 0
#define T_ALO TILE
#define T_BHI (2 * TILE)
#define T_BLO (3 * TILE)
#define STAGE_BYTES (4 * TILE)       // 32768 B
#define STAGES 3
#define GSMEM (STAGES * STAGE_BYTES) // 98304 B

__device__ __forceinline__ uint32_t swz(int r, int q) {
    return (uint32_t)(r * 64 + ((q ^ ((r >> 1) & 3)) << 4));
}

__device__ __forceinline__ void load_chunk(uint32_t sstage, const GP* __restrict__ p,
                                           int kt, int cy, int cx, int tid) {
    const bf16 *Ah, *Al;
    int ka, sA;
    if (kt < p->K1) { Ah = p->Ahi;  Al = p->Alo;  ka = kt;         sA = p->ldA1; }
    else            { Ah = p->A2hi; Al = p->A2lo; ka = kt - p->K1; sA = p->ldA2; }
    const bf16* Bh = p->Bhi;
    const bf16* Bl = p->Blo;
    const int sB = p->ldB;
    #pragma unroll
    for (int i = 0; i < 2; i++) {
        int u = tid + i * 256;       // 0..511
        int r = u >> 2, q = u & 3;
        uint32_t so = swz(r, q);
        size_t ga = (size_t)(cy + r) * sA + ka + q * 8;
        size_t gb = (size_t)(cx + r) * sB + kt + q * 8;
        cp_async16(sstage + T_AHI + so, Ah + ga);
        cp_async16(sstage + T_ALO + so, Al + ga);
        cp_async16(sstage + T_BHI + so, Bh + gb);
        cp_async16(sstage + T_BLO + so, Bl + gb);
    }
}

__global__ __launch_bounds__(256, 2)
void gemm_uni(GP p0, GP p1, int n0) {
    extern __shared__ char smem[];
    const uint32_t sb = smem_u32(smem);
    int id = blockIdx.x;
    const GP* __restrict__ p;
    if (id < n0) p = &p0;
    else { p = &p1; id -= n0; }

    const int tid  = threadIdx.x;
    const int lane = tid & 31;
    const int wid  = tid >> 5;
    const int wm   = wid >> 2;
    const int wn   = wid & 3;
    const int cx   = (id % p->gx) * BN;
    const int cy   = (id / p->gx) * BM;
    const int NCK  = p->Kloop >> 5;

    float acc[4][4][4];
    #pragma unroll
    for (int i = 0; i < 4; i++)
        #pragma unroll
        for (int j = 0; j < 4; j++)
            #pragma unroll
            for (int k = 0; k < 4; k++) acc[i][j][k] = 0.0f;

    const int arow = wm * 64 + (lane & 15);
    const int abit = (lane >> 4) & 1;
    const int asw  = (arow >> 1) & 3;
    const int brow = wn * 32 + (lane & 7) + ((lane & 16) ? 8 : 0);
    const int bbit = (lane >> 3) & 1;
    const int bsw  = (brow >> 1) & 3;
    uint32_t aofk[2], bofk[2];
    #pragma unroll
    for (int ks = 0; ks < 2; ks++) {
        aofk[ks] = (uint32_t)(arow * 64 + ((((ks << 1) | abit) ^ asw) << 4));
        bofk[ks] = (uint32_t)(brow * 64 + ((((ks << 1) | bbit) ^ bsw) << 4));
    }

    // prefetch chunks 0,1
    #pragma unroll
    for (int c = 0; c < STAGES - 1; c++) {
        if (c < NCK)
            load_chunk(sb + c * STAGE_BYTES, p, c * BK, cy, cx, tid);
        cp_commit();
    }

    int bufc = 0;
    for (int c = 0; c < NCK; c++) {
        if (c == NCK - 1) cp_wait<0>(); else cp_wait<1>();
        __syncthreads();
        if (c + 2 < NCK) {
            int nb = bufc + 2; if (nb >= STAGES) nb -= STAGES;
            load_chunk(sb + nb * STAGE_BYTES, p, (c + 2) * BK, cy, cx, tid);
            cp_commit();
        }

        const uint32_t st = sb + bufc * STAGE_BYTES;
        bufc++; if (bufc >= STAGES) bufc = 0;

        #pragma unroll
        for (int ks = 0; ks < 2; ks++) {
            uint32_t a[4][4], b[4][2];
            // acc += Ahi*Blo
            #pragma unroll
            for (int nf2 = 0; nf2 < 2; nf2++) {
                uint32_t r0, r1, r2, r3;
                ldsm_x4(st + T_BLO + bofk[ks] + nf2 * 1024, r0, r1, r2, r3);
                b[nf2 * 2 + 0][0] = r0; b[nf2 * 2 + 0][1] = r1;
                b[nf2 * 2 + 1][0] = r2; b[nf2 * 2 + 1][1] = r3;
            }
            #pragma unroll
            for (int mf = 0; mf < 4; mf++)
                ldsm_x4(st + T_AHI + aofk[ks] + mf * 1024,
                        a[mf][0], a[mf][1], a[mf][2], a[mf][3]);
            #pragma unroll
            for (int mf = 0; mf < 4; mf++)
                #pragma unroll
                for (int nf = 0; nf < 4; nf++)
                    mma_bf16(acc[mf][nf], a[mf], b[nf]);
            // acc += Ahi*Bhi
            #pragma unroll
            for (int nf2 = 0; nf2 < 2; nf2++) {
                uint32_t r0, r1, r2, r3;
                ldsm_x4(st + T_BHI + bofk[ks] + nf2 * 1024, r0, r1, r2, r3);
                b[nf2 * 2 + 0][0] = r0; b[nf2 * 2 + 0][1] = r1;
                b[nf2 * 2 + 1][0] = r2; b[nf2 * 2 + 1][1] = r3;
            }
            #pragma unroll
            for (int mf = 0; mf < 4; mf++)
                #pragma unroll
                for (int nf = 0; nf < 4; nf++)
                    mma_bf16(acc[mf][nf], a[mf], b[nf]);
            // acc += Alo*Bhi
            #pragma unroll
            for (int mf = 0; mf < 4; mf++)
                ldsm_x4(st + T_ALO + aofk[ks] + mf * 1024,
                        a[mf][0], a[mf][1], a[mf][2], a[mf][3]);
            #pragma unroll
            for (int mf = 0; mf < 4; mf++)
                #pragma unroll
                for (int nf = 0; nf < 4; nf++)
                    mma_bf16(acc[mf][nf], a[mf], b[nf]);
        }
        __syncthreads();
    }

    // ---------------- epilogue -----------------------------------------------
    const int gid = lane >> 2;
    const int tig = lane & 3;
    const int ldC = p->ldC;
    const int biasmode = p->biasmode;
    const int relu = p->relu;
    const int split = p->split;
    #pragma unroll
    for (int mf = 0; mf < 4; mf++) {
        const int row0 = cy + wm * 64 + mf * 16 + gid;
        float rb0 = 0.f, rb1 = 0.f;
        if (biasmode == 2) { rb0 = p->bias[row0]; rb1 = p->bias[row0 + 8]; }
        #pragma unroll
        for (int nf = 0; nf < 4; nf++) {
            const int col = cx + wn * 32 + nf * 8 + tig * 2;
            float v0 = acc[mf][nf][0], v1 = acc[mf][nf][1];
            float v2 = acc[mf][nf][2], v3 = acc[mf][nf][3];
            if (biasmode == 1) {
                float b0 = p->bias[col], b1 = p->bias[col + 1];
                v0 += b0; v1 += b1; v2 += b0; v3 += b1;
            } else if (biasmode == 2) {
                v0 += rb0; v1 += rb0; v2 += rb1; v3 += rb1;
            }
            if (relu) {
                v0 = fmaxf(v0, 0.f); v1 = fmaxf(v1, 0.f);
                v2 = fmaxf(v2, 0.f); v3 = fmaxf(v3, 0.f);
            }
            if (!split) {
                *(float2*)(p->Cf + (size_t)row0 * ldC + col)       = make_float2(v0, v1);
                *(float2*)(p->Cf + (size_t)(row0 + 8) * ldC + col) = make_float2(v2, v3);
            } else {
                bf16 h0 = __float2bfloat16(v0), h1 = __float2bfloat16(v1);
                bf16 h2 = __float2bfloat16(v2), h3 = __float2bfloat16(v3);
                bf16 l0 = __float2bfloat16(v0 - __bfloat162float(h0));
                bf16 l1 = __float2bfloat16(v1 - __bfloat162float(h1));
                bf16 l2 = __float2bfloat16(v2 - __bfloat162float(h2));
                bf16 l3 = __float2bfloat16(v3 - __bfloat162float(h3));
                __nv_bfloat162 hp0; hp0.x = h0; hp0.y = h1;
                __nv_bfloat162 hp1; hp1.x = h2; hp1.y = h3;
                __nv_bfloat162 lp0; lp0.x = l0; lp0.y = l1;
                __nv_bfloat162 lp1; lp1.x = l2; lp1.y = l3;
                *(__nv_bfloat162*)(p->Chi + (size_t)row0 * ldC + col)       = hp0;
                *(__nv_bfloat162*)(p->Chi + (size_t)(row0 + 8) * ldC + col) = hp1;
                *(__nv_bfloat162*)(p->Clo + (size_t)row0 * ldC + col)       = lp0;
                *(__nv_bfloat162*)(p->Clo + (size_t)(row0 + 8) * ldC + col) = lp1;
            }
        }
    }
}

// ---------------- elementwise kernels -----------------------------------------
__global__ void zero_kernel(float* p, int n) {
    int i = blockIdx.x * blockDim.x + threadIdx.x;
    if (i < n) p[i] = 0.0f;
}

__device__ __forceinline__ void split_store(bf16* hi, bf16* lo, size_t idx, float v) {
    bf16 h = __float2bfloat16(v);
    hi[idx] = h;
    lo[idx] = __float2bfloat16(v - __bfloat162float(h));
}

__device__ __forceinline__ __nv_bfloat162 pack_hi2(float a, float b) {
    __nv_bfloat162 r; r.x = __float2bfloat16(a); r.y = __float2bfloat16(b); return r;
}
__device__ __forceinline__ __nv_bfloat162 pack_lo2(float a, float b, __nv_bfloat162 h) {
    __nv_bfloat162 r;
    r.x = __float2bfloat16(a - __bfloat162float(h.x));
    r.y = __float2bfloat16(b - __bfloat162float(h.y));
    return r;
}

// -------- merged prep: colsum blocks (first) + weight transpose-splits --------
#define CS_ROWS 128
#define PR_CS   128
#define PR_WV   (PR_CS + 1024)
#define PR_W1   (PR_WV + 4096)
#define PR_W2   (PR_W1 + 8192)
__global__ void prep1_kernel(const float* __restrict__ X, float* __restrict__ colsum,
                             const float* __restrict__ Wv,
                             bf16* __restrict__ WvThi, bf16* __restrict__ WvTlo,
                             const float* __restrict__ W1,
                             bf16* __restrict__ W1Thi, bf16* __restrict__ W1Tlo,
                             const float* __restrict__ W2,
                             bf16* __restrict__ W2Thi, bf16* __restrict__ W2Tlo) {
    __shared__ float t[32][33];
    int id  = blockIdx.x;
    int tid = threadIdx.x;

    if (id < PR_CS) {
        int j  = (id & 3) * 256 + tid;
        int r0 = (id >> 2) * CS_ROWS;
        float inv = powf(10000.0f, -(float)(j & ~1) / (float)DD);
        bool odd = (j & 1);
        float s = 0.0f;
        #pragma unroll 4
        for (int i = 0; i < CS_ROWS; i++) {
            int pos = r0 + i;
            float arg = (float)pos * inv;
            float pe = odd ? cosf(arg) : sinf(arg);
            s += pe * X[(size_t)pos * DD + j];
        }
        atomicAdd(&colsum[j], s);
        return;
    }

    const float* src;
    bf16 *dhi, *dlo;
    int R, C, nbx;
    if (id < PR_WV)      { src = Wv; dhi = WvThi; dlo = WvTlo; R = DD;     C = DD; nbx = DD / 32; id -= PR_CS; }
    else if (id < PR_W1) { src = W1; dhi = W1Thi; dlo = W1Tlo; R = 2 * DD; C = HH; nbx = HH / 32; id -= PR_WV; }
    else                 { src = W2; dhi = W2Thi; dlo = W2Tlo; R = HH;     C = NN; nbx = NN / 32; id -= PR_W1; }
    int bx = (id % nbx) * 32;
    int by = (id / nbx) * 32;
    int tx = tid & 31, ty = tid >> 5;
    #pragma unroll
    for (int i = 0; i < 4; i++)
        t[ty + i * 8][tx] = src[(size_t)(by + ty + i * 8) * C + bx + tx];
    __syncthreads();
    #pragma unroll
    for (int i = 0; i < 4; i++) {
        float v = t[tx][ty + i * 8];
        split_store(dhi, dlo, (size_t)(bx + ty + i * 8) * R + by + tx, v);
    }
}

// loo + X split, 4 elements per thread (two even/odd pairs)
__global__ void loo_split_kernel(const float* __restrict__ X,
                                 const float* __restrict__ colsum,
                                 bf16* __restrict__ lhi, bf16* __restrict__ llo,
                                 bf16* __restrict__ xhi, bf16* __restrict__ xlo) {
    size_t idx4 = ((size_t)blockIdx.x * blockDim.x + threadIdx.x) * 4;
    int row = (int)(idx4 >> 10);
    int j   = (int)(idx4 & 1023);            // even, j and j+2 pairs
    float4 x4 = *(const float4*)(X + idx4);
    const float r1 = 1.0f / (float)(NN - 1);
    float inv0 = powf(10000.0f, -(float)j / (float)DD);
    float inv1 = powf(10000.0f, -(float)(j + 2) / (float)DD);
    float s0, c0, s1, c1;
    sincosf((float)row * inv0, &s0, &c0);
    sincosf((float)row * inv1, &s1, &c1);
    float l0 = (colsum[j]     - s0 * x4.x) * r1;
    float l1 = (colsum[j + 1] - c0 * x4.y) * r1;
    float l2 = (colsum[j + 2] - s1 * x4.z) * r1;
    float l3 = (colsum[j + 3] - c1 * x4.w) * r1;
    __nv_bfloat162 xh0 = pack_hi2(x4.x, x4.y), xh1 = pack_hi2(x4.z, x4.w);
    __nv_bfloat162 xl0 = pack_lo2(x4.x, x4.y, xh0), xl1 = pack_lo2(x4.z, x4.w, xh1);
    __nv_bfloat162 lh0 = pack_hi2(l0, l1), lh1 = pack_hi2(l2, l3);
    __nv_bfloat162 ll0 = pack_lo2(l0, l1, lh0), ll1 = pack_lo2(l2, l3, lh1);
    *(__nv_bfloat162*)(xhi + idx4)     = xh0;
    *(__nv_bfloat162*)(xhi + idx4 + 2) = xh1;
    *(__nv_bfloat162*)(xlo + idx4)     = xl0;
    *(__nv_bfloat162*)(xlo + idx4 + 2) = xl1;
    *(__nv_bfloat162*)(lhi + idx4)     = lh0;
    *(__nv_bfloat162*)(lhi + idx4 + 2) = lh1;
    *(__nv_bfloat162*)(llo + idx4)     = ll0;
    *(__nv_bfloat162*)(llo + idx4 + 2) = ll1;
}

// row softmax over scoresA+scoresB WITHOUT max-subtraction (scores bounded;
// exp(s) cannot overflow fp32 here; softmax value identical). One gmem pass.
__global__ void softmax_split_kernel(const float* __restrict__ SA,
                                     const float* __restrict__ SB,
                                     bf16* __restrict__ ahi, bf16* __restrict__ alo, int n) {
    __shared__ float red[8];
    __shared__ float buf[4096];
    const float* rowA = SA + (size_t)blockIdx.x * n;
    const float* rowB = SB + (size_t)blockIdx.x * n;
    int tid = threadIdx.x;
    int lane = tid & 31, warp = tid >> 5;

    float s = 0.0f;
    for (int j = tid * 2; j < n; j += 512) {
        float2 a = *(const float2*)(rowA + j);
        float2 b = *(const float2*)(rowB + j);
        float e0 = __expf(a.x + b.x);
        float e1 = __expf(a.y + b.y);
        buf[j] = e0; buf[j + 1] = e1;
        s += e0 + e1;
    }
    #pragma unroll
    for (int o = 16; o > 0; o >>= 1) s += __shfl_xor_sync(0xffffffffu, s, o);
    if (lane == 0) red[warp] = s;
    __syncthreads();
    if (tid < 8) {
        float v = red[tid];
        #pragma unroll
        for (int o = 4; o > 0; o >>= 1) v += __shfl_xor_sync(0xffu, v, o);
        if (tid == 0) red[0] = v;
    }
    __syncthreads();
    float inv = 1.0f / red[0];
    size_t base = (size_t)blockIdx.x * n;
    for (int j = tid * 2; j < n; j += 512) {
        float a0 = buf[j] * inv;
        float a1 = buf[j + 1] * inv;
        __nv_bfloat162 h = pack_hi2(a0, a1);
        __nv_bfloat162 l = pack_lo2(a0, a1, h);
        *(__nv_bfloat162*)(ahi + base + j) = h;
        *(__nv_bfloat162*)(alo + base + j) = l;
    }
}

// ---------------- driver ------------------------------------------------------
extern "C" void kernel_launch(void* const* d_in, const int* in_sizes, int n_in,
                              void* d_out, int out_size) {
    const float* X  = (const float*)d_in[0];
    const float* Wv = (const float*)d_in[2];
    const float* bv = (const float*)d_in[3];
    const float* W1 = (const float*)d_in[4];
    const float* b1 = (const float*)d_in[5];
    const float* W2 = (const float*)d_in[6];
    const float* b2 = (const float*)d_in[7];
    float* out = (float*)d_out;

    void* p;
    cudaGetSymbolAddress(&p, g_colsum);  float* colsum  = (float*)p;
    cudaGetSymbolAddress(&p, g_scoresA); float* scoresA = (float*)p;
    cudaGetSymbolAddress(&p, g_scoresB); float* scoresB = (float*)p;
    cudaGetSymbolAddress(&p, g_Xhi);    bf16* Xhi   = (bf16*)p;
    cudaGetSymbolAddress(&p, g_Xlo);    bf16* Xlo   = (bf16*)p;
    cudaGetSymbolAddress(&p, g_loohi);  bf16* loohi = (bf16*)p;
    cudaGetSymbolAddress(&p, g_loolo);  bf16* loolo = (bf16*)p;
    cudaGetSymbolAddress(&p, g_WvThi);  bf16* WvThi = (bf16*)p;
    cudaGetSymbolAddress(&p, g_WvTlo);  bf16* WvTlo = (bf16*)p;
    cudaGetSymbolAddress(&p, g_W1Thi);  bf16* W1Thi = (bf16*)p;
    cudaGetSymbolAddress(&p, g_W1Tlo);  bf16* W1Tlo = (bf16*)p;
    cudaGetSymbolAddress(&p, g_hidhi);  bf16* hdhi  = (bf16*)p;
    cudaGetSymbolAddress(&p, g_hidlo);  bf16* hdlo  = (bf16*)p;
    cudaGetSymbolAddress(&p, g_W2Thi);  bf16* W2Thi = (bf16*)p;
    cudaGetSymbolAddress(&p, g_W2Tlo);  bf16* W2Tlo = (bf16*)p;
    cudaGetSymbolAddress(&p, g_atthi);  bf16* athi  = (bf16*)p;
    cudaGetSymbolAddress(&p, g_attlo);  bf16* atlo  = (bf16*)p;
    cudaGetSymbolAddress(&p, g_VThi);   bf16* VThi  = (bf16*)p;
    cudaGetSymbolAddress(&p, g_VTlo);   bf16* VTlo  = (bf16*)p;

    cudaFuncSetAttribute(gemm_uni, cudaFuncAttributeMaxDynamicSharedMemorySize, GSMEM);

    // --- operand prep --------------------------------------------------------
    zero_kernel<<<4, 256>>>(colsum, DD);
    prep1_kernel<<<PR_W2, 256>>>(X, colsum, Wv, WvThi, WvTlo, W1, W1Thi, W1Tlo, W2, W2Thi, W2Tlo);
    loo_split_kernel<<<(NN * DD / 4) / 256, 256>>>(X, colsum, loohi, loolo, Xhi, Xlo);

    // --- job descriptions -----------------------------------------------------
    GP g1;
    g1.Ahi = WvThi; g1.Alo = WvTlo; g1.A2hi = WvThi; g1.A2lo = WvTlo;
    g1.Bhi = Xhi;   g1.Blo = Xlo;
    g1.bias = bv;   g1.Cf = nullptr; g1.Chi = VThi; g1.Clo = VTlo;
    g1.gx = NN / BN;
    g1.ldA1 = DD; g1.ldA2 = DD; g1.ldB = DD; g1.ldC = NN;
    g1.Kloop = DD; g1.K1 = DD;
    g1.biasmode = 2; g1.relu = 0; g1.split = 1;

    GP g2;
    g2.Ahi = Xhi; g2.Alo = Xlo; g2.A2hi = loohi; g2.A2lo = loolo;
    g2.Bhi = W1Thi; g2.Blo = W1Tlo;
    g2.bias = b1; g2.Cf = nullptr; g2.Chi = hdhi; g2.Clo = hdlo;
    g2.gx = HH / BN;
    g2.ldA1 = DD; g2.ldA2 = DD; g2.ldB = 2 * DD; g2.ldC = HH;
    g2.Kloop = 2 * DD; g2.K1 = DD;
    g2.biasmode = 1; g2.relu = 1; g2.split = 1;

    GP g3a;
    g3a.Ahi = hdhi; g3a.Alo = hdlo; g3a.A2hi = hdhi; g3a.A2lo = hdlo;
    g3a.Bhi = W2Thi; g3a.Blo = W2Tlo;
    g3a.bias = b2; g3a.Cf = scoresA; g3a.Chi = nullptr; g3a.Clo = nullptr;
    g3a.gx = NN / BN;
    g3a.ldA1 = HH; g3a.ldA2 = HH; g3a.ldB = HH; g3a.ldC = NN;
    g3a.Kloop = HH / 2; g3a.K1 = HH / 2;
    g3a.biasmode = 1; g3a.relu = 0; g3a.split = 0;
    GP g3b = g3a;
    g3b.Ahi = hdhi + HH / 2;  g3b.Alo = hdlo + HH / 2;
    g3b.A2hi = g3b.Ahi;       g3b.A2lo = g3b.Alo;
    g3b.Bhi = W2Thi + HH / 2; g3b.Blo = W2Tlo + HH / 2;
    g3b.Cf = scoresB;
    g3b.biasmode = 0;

    GP g4;
    g4.Ahi = athi; g4.Alo = atlo; g4.A2hi = athi; g4.A2lo = atlo;
    g4.Bhi = VThi; g4.Blo = VTlo;
    g4.bias = nullptr; g4.Cf = out; g4.Chi = nullptr; g4.Clo = nullptr;
    g4.gx = DD / BN;
    g4.ldA1 = NN; g4.ldA2 = NN; g4.ldB = NN; g4.ldC = DD;
    g4.Kloop = NN; g4.K1 = NN;
    g4.biasmode = 0; g4.relu = 0; g4.split = 0;

    // --- schedule (longest-job-first within each launch) ----------------------
    {
        int n2 = g2.gx * (NN / BM);                      // 512
        int n1 = g1.gx * (DD / BM);                      // 256
        gemm_uni<<<n2 + n1, 256, GSMEM>>>(g2, g1, n2);
    }
    {
        int n3 = (NN / BN) * (NN / BM);                  // 1024 each
        gemm_uni<<<2 * n3, 256, GSMEM>>>(g3a, g3b, n3);
    }
    softmax_split_kernel<<<NN, 256>>>(scoresA, scoresB, athi, atlo, NN);
    {
        int n4 = g4.gx * (NN / BM);                      // 256
        gemm_uni<<<n4, 256, GSMEM>>>(g4, g4, n4);
    }
}